// round 1
// baseline (speedup 1.0000x reference)
#include <cuda_runtime.h>
#include <math.h>

#define BSZ   2
#define TSEQ  2048
#define DMOD  1024
#define NH    16
#define HDIM  64
#define MTOK  (BSZ*TSEQ)      /* 4096 */

// Scratch (device globals — no allocations allowed)
__device__ float g_q[(size_t)BSZ*NH*TSEQ*HDIM];   // [B,H,T,64]
__device__ float g_k[(size_t)BSZ*NH*TSEQ*HDIM];
__device__ float g_v[(size_t)BSZ*NH*TSEQ*HDIM];
__device__ float g_att[(size_t)MTOK*DMOD];        // [B,T,D]

// ---------------------------------------------------------------------------
// 64x64 register-blocked fp32 GEMM body: C_tile = A[M,K] @ W[K,N]
// 256 threads, each owns a 4x4 micro-tile. K-tile = 16.
// ---------------------------------------------------------------------------
__device__ __forceinline__ void gemm_body(const float* __restrict__ A,
                                          const float* __restrict__ W,
                                          int K, int N, float acc[4][4]) {
    __shared__ float As[64][20];   // padded rows (80B, 16B-aligned)
    __shared__ float Bs[16][64];
    const int tid = threadIdx.x;
    const int tx  = tid & 15;
    const int ty  = tid >> 4;
    const int m0  = blockIdx.y * 64;
    const int n0  = blockIdx.x * 64;

    for (int k0 = 0; k0 < K; k0 += 16) {
        // A tile: 64(m) x 16(k). One float4 per thread along k.
        {
            int m   = tid >> 2;
            int kk0 = (tid & 3) * 4;
            float4 a = *(const float4*)&A[(size_t)(m0 + m) * K + k0 + kk0];
            *(float4*)&As[m][kk0] = a;
        }
        // B tile: 16(k) x 64(n). One float4 per thread along n (coalesced).
        {
            int kk = tid >> 4;
            int n4 = (tid & 15) * 4;
            float4 b = *(const float4*)&W[(size_t)(k0 + kk) * N + n0 + n4];
            *(float4*)&Bs[kk][n4] = b;
        }
        __syncthreads();
        #pragma unroll
        for (int kk = 0; kk < 16; kk++) {
            float a0 = As[ty*4+0][kk];
            float a1 = As[ty*4+1][kk];
            float a2 = As[ty*4+2][kk];
            float a3 = As[ty*4+3][kk];
            float4 b = *(const float4*)&Bs[kk][tx*4];
            acc[0][0] += a0*b.x; acc[0][1] += a0*b.y; acc[0][2] += a0*b.z; acc[0][3] += a0*b.w;
            acc[1][0] += a1*b.x; acc[1][1] += a1*b.y; acc[1][2] += a1*b.z; acc[1][3] += a1*b.w;
            acc[2][0] += a2*b.x; acc[2][1] += a2*b.y; acc[2][2] += a2*b.z; acc[2][3] += a2*b.w;
            acc[3][0] += a3*b.x; acc[3][1] += a3*b.y; acc[3][2] += a3*b.z; acc[3][3] += a3*b.w;
        }
        __syncthreads();
    }
}

// QKV GEMM: qkv = x @ W_kqv + b_kqv, scattered into g_q/g_k/g_v as [B,H,T,64].
// A 64-wide n-tile never crosses a head boundary (1024 % 64 == 0).
__global__ __launch_bounds__(256) void gemm_qkv_k(const float* __restrict__ x,
                                                  const float* __restrict__ W,
                                                  const float* __restrict__ bias) {
    float acc[4][4] = {};
    gemm_body(x, W, DMOD, 3*DMOD, acc);
    const int tx = threadIdx.x & 15;
    const int ty = threadIdx.x >> 4;
    const int m0 = blockIdx.y * 64;
    const int n0 = blockIdx.x * 64;
    const int which = n0 >> 10;           // 0:q 1:k 2:v
    const int h     = (n0 & 1023) >> 6;
    float* dst = (which == 0) ? g_q : ((which == 1) ? g_k : g_v);
    float4 bb = *(const float4*)&bias[n0 + tx*4];
    #pragma unroll
    for (int i = 0; i < 4; i++) {
        int m = m0 + ty*4 + i;
        int b = m >> 11;                  // /TSEQ
        int t = m & (TSEQ - 1);
        size_t o = ((size_t)(b*NH + h)*TSEQ + t)*HDIM + tx*4;
        float4 r;
        r.x = acc[i][0] + bb.x; r.y = acc[i][1] + bb.y;
        r.z = acc[i][2] + bb.z; r.w = acc[i][3] + bb.w;
        *(float4*)&dst[o] = r;
    }
}

// Output projection: out = g_att @ W_proj + b_proj
__global__ __launch_bounds__(256) void gemm_proj_k(const float* __restrict__ W,
                                                   const float* __restrict__ bias,
                                                   float* __restrict__ C) {
    float acc[4][4] = {};
    gemm_body(g_att, W, DMOD, DMOD, acc);
    const int tx = threadIdx.x & 15;
    const int ty = threadIdx.x >> 4;
    const int m0 = blockIdx.y * 64;
    const int n0 = blockIdx.x * 64;
    float4 bb = *(const float4*)&bias[n0 + tx*4];
    #pragma unroll
    for (int i = 0; i < 4; i++) {
        int m = m0 + ty*4 + i;
        float4 r;
        r.x = acc[i][0] + bb.x; r.y = acc[i][1] + bb.y;
        r.z = acc[i][2] + bb.z; r.w = acc[i][3] + bb.w;
        *(float4*)&C[(size_t)m * DMOD + n0 + tx*4] = r;
    }
}

// ---------------------------------------------------------------------------
// Flash-style causal attention.
// Grid: (T/64 q-tiles, B*H). 256 threads = 64 rows x 4 sub-lanes.
// Each thread: full q row in registers (16 float4), 16 keys (j = sub + 4*jj),
// 16 output dims (d = sub*16 + i). Online softmax; per-row reductions via
// shfl over the 4 consecutive lanes of a row. P reuses the K smem buffer.
// ---------------------------------------------------------------------------
#define LDS_STRIDE 68   // 64 + 4 pad: float4-aligned rows, conflict-free

__global__ __launch_bounds__(256) void attn_k() {
    __shared__ float ks[64 * LDS_STRIDE];   // K tile, then reused for P
    __shared__ float vs[64 * LDS_STRIDE];

    const int qt  = blockIdx.x;
    const int bh  = blockIdx.y;
    const int tid = threadIdx.x;
    const int row = tid >> 2;
    const int sub = tid & 3;

    const float* Qb = g_q + (size_t)bh * TSEQ * HDIM + (size_t)qt * 64 * HDIM;
    const float* Kb = g_k + (size_t)bh * TSEQ * HDIM;
    const float* Vb = g_v + (size_t)bh * TSEQ * HDIM;

    // Q row -> registers
    float4 qv[16];
    {
        const float4* qr = (const float4*)(Qb + row * HDIM);
        #pragma unroll
        for (int d4 = 0; d4 < 16; d4++) qv[d4] = qr[d4];
    }

    float mi = -1e30f, li = 0.0f;
    float acc[16];
    #pragma unroll
    for (int i = 0; i < 16; i++) acc[i] = 0.0f;

    const int q_glob = qt * 64 + row;

    for (int kt = 0; kt <= qt; kt++) {
        __syncthreads();   // prior iteration done reading ks/vs
        {
            const float4* Kt = (const float4*)(Kb + (size_t)kt * 64 * HDIM);
            const float4* Vt = (const float4*)(Vb + (size_t)kt * 64 * HDIM);
            #pragma unroll
            for (int r = 0; r < 4; r++) {
                int f  = tid + r * 256;        // float4 index 0..1023
                int rr = f >> 4, c4 = f & 15;
                *(float4*)&ks[rr * LDS_STRIDE + c4 * 4] = Kt[f];
                *(float4*)&vs[rr * LDS_STRIDE + c4 * 4] = Vt[f];
            }
        }
        __syncthreads();

        // Scores for this thread's 16 keys
        float s[16];
        #pragma unroll
        for (int jj = 0; jj < 16; jj++) {
            int j = sub + jj * 4;
            const float* kr = &ks[j * LDS_STRIDE];
            float s0 = 0.f, s1 = 0.f, s2 = 0.f, s3 = 0.f;
            #pragma unroll
            for (int d4 = 0; d4 < 16; d4++) {
                float4 ka = *(const float4*)&kr[d4 * 4];
                s0 += qv[d4].x * ka.x;
                s1 += qv[d4].y * ka.y;
                s2 += qv[d4].z * ka.z;
                s3 += qv[d4].w * ka.w;
            }
            float sv = (s0 + s1 + s2 + s3) * 0.125f;   // 1/sqrt(64)
            if (kt * 64 + j > q_glob) sv = -1e30f;     // causal mask
            s[jj] = sv;
        }

        // Row max across this thread's keys + the other 3 sub-lanes
        float mt = s[0];
        #pragma unroll
        for (int jj = 1; jj < 16; jj++) mt = fmaxf(mt, s[jj]);
        mt = fmaxf(mt, __shfl_xor_sync(0xffffffffu, mt, 1));
        mt = fmaxf(mt, __shfl_xor_sync(0xffffffffu, mt, 2));

        float mnew = fmaxf(mi, mt);
        float corr = __expf(mi - mnew);
        float lsum = 0.0f;
        #pragma unroll
        for (int jj = 0; jj < 16; jj++) {
            s[jj] = __expf(s[jj] - mnew);
            lsum += s[jj];
        }
        lsum += __shfl_xor_sync(0xffffffffu, lsum, 1);
        lsum += __shfl_xor_sync(0xffffffffu, lsum, 2);
        li = li * corr + lsum;
        mi = mnew;
        #pragma unroll
        for (int i = 0; i < 16; i++) acc[i] *= corr;

        __syncthreads();   // everyone done reading ks (scores)
        #pragma unroll
        for (int jj = 0; jj < 16; jj++)
            ks[row * LDS_STRIDE + sub + jj * 4] = s[jj];   // P in K's buffer
        __syncthreads();

        // acc += P @ V  (this thread: all 64 keys, its 16 output dims)
        {
            const float* pr = &ks[row * LDS_STRIDE];
            #pragma unroll 4
            for (int j = 0; j < 64; j++) {
                float p = pr[j];
                const float* vr = &vs[j * LDS_STRIDE + sub * 16];
                #pragma unroll
                for (int i4 = 0; i4 < 4; i4++) {
                    float4 vvv = *(const float4*)&vr[i4 * 4];
                    acc[i4*4+0] += p * vvv.x;
                    acc[i4*4+1] += p * vvv.y;
                    acc[i4*4+2] += p * vvv.z;
                    acc[i4*4+3] += p * vvv.w;
                }
            }
        }
    }

    // Normalize and write to [B,T,D] layout
    const int b = bh / NH, h = bh % NH;
    const float inv = 1.0f / li;
    size_t ob = ((size_t)b * TSEQ + q_glob) * DMOD + h * HDIM + sub * 16;
    #pragma unroll
    for (int i4 = 0; i4 < 4; i4++) {
        float4 o;
        o.x = acc[i4*4+0] * inv; o.y = acc[i4*4+1] * inv;
        o.z = acc[i4*4+2] * inv; o.w = acc[i4*4+3] * inv;
        *(float4*)&g_att[ob + i4 * 4] = o;
    }
}

// ---------------------------------------------------------------------------
extern "C" void kernel_launch(void* const* d_in, const int* in_sizes, int n_in,
                              void* d_out, int out_size) {
    (void)in_sizes; (void)n_in; (void)out_size;
    const float* x     = (const float*)d_in[0];
    const float* Wkqv  = (const float*)d_in[1];
    const float* bkqv  = (const float*)d_in[2];
    const float* Wproj = (const float*)d_in[3];
    const float* bproj = (const float*)d_in[4];
    float* out = (float*)d_out;

    gemm_qkv_k <<<dim3(3*DMOD/64, MTOK/64), 256>>>(x, Wkqv, bkqv);
    attn_k     <<<dim3(TSEQ/64, BSZ*NH),    256>>>();
    gemm_proj_k<<<dim3(DMOD/64,  MTOK/64),  256>>>(Wproj, bproj, out);
}

// round 3
// speedup vs baseline: 2.0237x; 2.0237x over previous
#include <cuda_runtime.h>
#include <math.h>

#define BSZ   2
#define TSEQ  2048
#define DMOD  1024
#define NH    16
#define HDIM  64
#define MTOK  (BSZ*TSEQ)      /* 4096 */

// Scratch (device globals — no allocations allowed)
__device__ float g_q[(size_t)BSZ*NH*TSEQ*HDIM];   // [B,H,T,64] (pre-scaled by 1/8)
__device__ float g_k[(size_t)BSZ*NH*TSEQ*HDIM];
__device__ float g_v[(size_t)BSZ*NH*TSEQ*HDIM];
__device__ float g_att[(size_t)MTOK*DMOD];        // [B,T,D]

// ===========================================================================
// 128x128x16 double-buffered fp32 GEMM body. 256 threads, 8x8 per thread
// (split 4+4 strided by 64 to keep LDS conflict-free). A stored transposed
// in smem with stride 132 (conflict-free scalar transpose stores).
// ===========================================================================
#define TK 16

struct GemmSmem {
    float As[2][TK][132];
    float Bs[2][TK][128];
};

__device__ __forceinline__ void gemm128_body(const float* __restrict__ A,
                                             const float* __restrict__ W,
                                             int K, int N, float acc[8][8]) {
    __shared__ GemmSmem sm;
    const int tid = threadIdx.x;
    const int tx  = tid & 15;
    const int ty  = tid >> 4;
    const int m0  = blockIdx.y * 128;
    const int n0  = blockIdx.x * 128;

    const int am = tid >> 2;          // A: row within tile for this thread
    const int akq = (tid & 3) * 4;    // A: k-quad start
    const int bkr = tid >> 5;         // B: k row (two of them, +8)
    const int bnq = (tid & 31) * 4;   // B: col start

    // Preload tile 0
    {
        float4 pa0 = *(const float4*)&A[(size_t)(m0 + am) * K + akq];
        float4 pa1 = *(const float4*)&A[(size_t)(m0 + 64 + am) * K + akq];
        float4 pb0 = *(const float4*)&W[(size_t)bkr * N + n0 + bnq];
        float4 pb1 = *(const float4*)&W[(size_t)(bkr + 8) * N + n0 + bnq];
        sm.As[0][akq+0][am] = pa0.x; sm.As[0][akq+1][am] = pa0.y;
        sm.As[0][akq+2][am] = pa0.z; sm.As[0][akq+3][am] = pa0.w;
        sm.As[0][akq+0][64+am] = pa1.x; sm.As[0][akq+1][64+am] = pa1.y;
        sm.As[0][akq+2][64+am] = pa1.z; sm.As[0][akq+3][64+am] = pa1.w;
        *(float4*)&sm.Bs[0][bkr][bnq]   = pb0;
        *(float4*)&sm.Bs[0][bkr+8][bnq] = pb1;
    }
    __syncthreads();

    const int nkt = K / TK;
    for (int kt = 0; kt < nkt; kt++) {
        const int cur = kt & 1, nxt = cur ^ 1;
        float4 pa0, pa1, pb0, pb1;
        if (kt + 1 < nkt) {
            int k0 = (kt + 1) * TK;
            pa0 = *(const float4*)&A[(size_t)(m0 + am) * K + k0 + akq];
            pa1 = *(const float4*)&A[(size_t)(m0 + 64 + am) * K + k0 + akq];
            pb0 = *(const float4*)&W[(size_t)(k0 + bkr) * N + n0 + bnq];
            pb1 = *(const float4*)&W[(size_t)(k0 + bkr + 8) * N + n0 + bnq];
        }
        #pragma unroll
        for (int kk = 0; kk < TK; kk++) {
            float4 a0 = *(const float4*)&sm.As[cur][kk][ty*4];
            float4 a1 = *(const float4*)&sm.As[cur][kk][64 + ty*4];
            float4 b0 = *(const float4*)&sm.Bs[cur][kk][tx*4];
            float4 b1 = *(const float4*)&sm.Bs[cur][kk][64 + tx*4];
            float a[8] = {a0.x,a0.y,a0.z,a0.w,a1.x,a1.y,a1.z,a1.w};
            float b[8] = {b0.x,b0.y,b0.z,b0.w,b1.x,b1.y,b1.z,b1.w};
            #pragma unroll
            for (int i = 0; i < 8; i++)
                #pragma unroll
                for (int j = 0; j < 8; j++)
                    acc[i][j] += a[i] * b[j];
        }
        __syncthreads();
        if (kt + 1 < nkt) {
            sm.As[nxt][akq+0][am] = pa0.x; sm.As[nxt][akq+1][am] = pa0.y;
            sm.As[nxt][akq+2][am] = pa0.z; sm.As[nxt][akq+3][am] = pa0.w;
            sm.As[nxt][akq+0][64+am] = pa1.x; sm.As[nxt][akq+1][64+am] = pa1.y;
            sm.As[nxt][akq+2][64+am] = pa1.z; sm.As[nxt][akq+3][64+am] = pa1.w;
            *(float4*)&sm.Bs[nxt][bkr][bnq]   = pb0;
            *(float4*)&sm.Bs[nxt][bkr+8][bnq] = pb1;
            __syncthreads();
        }
    }
}

// QKV GEMM: qkv = x @ W_kqv + b_kqv, scattered to g_q/g_k/g_v [B,H,T,64].
// Q is pre-scaled by 1/sqrt(64) here.
__global__ __launch_bounds__(256) void gemm_qkv_k(const float* __restrict__ x,
                                                  const float* __restrict__ W,
                                                  const float* __restrict__ bias) {
    float acc[8][8] = {};
    gemm128_body(x, W, DMOD, 3*DMOD, acc);
    const int tx = threadIdx.x & 15;
    const int ty = threadIdx.x >> 4;
    const int m0 = blockIdx.y * 128;
    const int n0 = blockIdx.x * 128;
    const int which = n0 >> 10;           // tile never crosses q/k/v boundary
    float* dst = (which == 0) ? g_q : ((which == 1) ? g_k : g_v);
    const float qscale = (which == 0) ? 0.125f : 1.0f;
    #pragma unroll
    for (int jh = 0; jh < 2; jh++) {
        int col0 = n0 + jh*64 + tx*4;
        int h = (col0 & 1023) >> 6;
        float4 bb = *(const float4*)&bias[col0];
        #pragma unroll
        for (int ih = 0; ih < 2; ih++) {
            #pragma unroll
            for (int ii = 0; ii < 4; ii++) {
                int m = m0 + ih*64 + ty*4 + ii;
                int b = m >> 11;
                int t = m & (TSEQ - 1);
                size_t o = ((size_t)(b*NH + h)*TSEQ + t)*HDIM + (col0 & 63);
                float4 r;
                r.x = (acc[ih*4+ii][jh*4+0] + bb.x) * qscale;
                r.y = (acc[ih*4+ii][jh*4+1] + bb.y) * qscale;
                r.z = (acc[ih*4+ii][jh*4+2] + bb.z) * qscale;
                r.w = (acc[ih*4+ii][jh*4+3] + bb.w) * qscale;
                *(float4*)&dst[o] = r;
            }
        }
    }
}

// Output projection: out = g_att @ W_proj + b_proj
__global__ __launch_bounds__(256) void gemm_proj_k(const float* __restrict__ W,
                                                   const float* __restrict__ bias,
                                                   float* __restrict__ C) {
    float acc[8][8] = {};
    gemm128_body(g_att, W, DMOD, DMOD, acc);
    const int tx = threadIdx.x & 15;
    const int ty = threadIdx.x >> 4;
    const int m0 = blockIdx.y * 128;
    const int n0 = blockIdx.x * 128;
    #pragma unroll
    for (int jh = 0; jh < 2; jh++) {
        float4 bb = *(const float4*)&bias[n0 + jh*64 + tx*4];
        #pragma unroll
        for (int ih = 0; ih < 2; ih++) {
            #pragma unroll
            for (int ii = 0; ii < 4; ii++) {
                int m = m0 + ih*64 + ty*4 + ii;
                float4 r;
                r.x = acc[ih*4+ii][jh*4+0] + bb.x;
                r.y = acc[ih*4+ii][jh*4+1] + bb.y;
                r.z = acc[ih*4+ii][jh*4+2] + bb.z;
                r.w = acc[ih*4+ii][jh*4+3] + bb.w;
                *(float4*)&C[(size_t)m * DMOD + n0 + jh*64 + tx*4] = r;
            }
        }
    }
}

// ===========================================================================
// GEMM-ified flash attention. 64x64 tiles, 256 threads (16x16), 4x4 per
// thread for both QK^T and PV. XOR-swizzled smem (stride 64, quad ^= (r>>2)&7)
// -> conflict-free for row & "column-row" access patterns; exactly 48KB.
// P reuses the K buffer. Q pre-scaled by 1/8 in the QKV epilogue.
// ===========================================================================
#define SWIDX(r,q) (((r) << 6) + ((((q) ^ (((r) >> 2) & 7))) << 2))

__global__ __launch_bounds__(256) void attn_k() {
    __shared__ float sQ[64*64];
    __shared__ float sK[64*64];   // reused for P after scores
    __shared__ float sV[64*64];

    const int qt  = blockIdx.x;
    const int bh  = blockIdx.y;
    const int tid = threadIdx.x;
    const int tx  = tid & 15;
    const int ty  = tid >> 4;

    const float* Qb = g_q + (size_t)bh * TSEQ * HDIM + (size_t)qt * 64 * HDIM;
    const float* Kb = g_k + (size_t)bh * TSEQ * HDIM;
    const float* Vb = g_v + (size_t)bh * TSEQ * HDIM;

    // Load Q tile (swizzled)
    {
        const float4* Qt = (const float4*)Qb;
        #pragma unroll
        for (int r = 0; r < 4; r++) {
            int f = tid + r * 256;          // quad index 0..1023
            int row = f >> 4, q = f & 15;
            *(float4*)&sQ[SWIDX(row, q)] = Qt[f];
        }
    }

    float m[4], l[4], acc[4][4];
    #pragma unroll
    for (int i = 0; i < 4; i++) {
        m[i] = -1e30f; l[i] = 0.0f;
        #pragma unroll
        for (int j = 0; j < 4; j++) acc[i][j] = 0.0f;
    }

    for (int kt = 0; kt <= qt; kt++) {
        __syncthreads();   // prev PV done with sV/sK(P); sQ ready on iter 0
        {
            const float4* Kt = (const float4*)(Kb + (size_t)kt * 64 * HDIM);
            const float4* Vt = (const float4*)(Vb + (size_t)kt * 64 * HDIM);
            #pragma unroll
            for (int r = 0; r < 4; r++) {
                int f = tid + r * 256;
                int row = f >> 4, q = f & 15;
                *(float4*)&sK[SWIDX(row, q)] = Kt[f];
                *(float4*)&sV[SWIDX(row, q)] = Vt[f];
            }
        }
        __syncthreads();

        // --- scores: s[i][j] = sum_d Q[ty*4+i][d] * K[tx*4+j][d]
        float s[4][4] = {};
        #pragma unroll
        for (int q4 = 0; q4 < 16; q4++) {
            float4 qa[4], ka[4];
            #pragma unroll
            for (int i = 0; i < 4; i++)
                qa[i] = *(const float4*)&sQ[SWIDX(ty*4+i, q4)];
            #pragma unroll
            for (int j = 0; j < 4; j++)
                ka[j] = *(const float4*)&sK[SWIDX(tx*4+j, q4)];
            #pragma unroll
            for (int i = 0; i < 4; i++)
                #pragma unroll
                for (int j = 0; j < 4; j++)
                    s[i][j] += qa[i].x*ka[j].x + qa[i].y*ka[j].y
                             + qa[i].z*ka[j].z + qa[i].w*ka[j].w;
        }

        // --- causal mask (only on the diagonal tile)
        if (kt == qt) {
            #pragma unroll
            for (int i = 0; i < 4; i++) {
                int rg = ty*4 + i;
                #pragma unroll
                for (int j = 0; j < 4; j++)
                    if (tx*4 + j > rg) s[i][j] = -1e30f;
            }
        }

        // --- online softmax (row reductions across the 16 tx lanes)
        #pragma unroll
        for (int i = 0; i < 4; i++) {
            float mt = fmaxf(fmaxf(s[i][0], s[i][1]), fmaxf(s[i][2], s[i][3]));
            mt = fmaxf(mt, __shfl_xor_sync(0xffffffffu, mt, 1));
            mt = fmaxf(mt, __shfl_xor_sync(0xffffffffu, mt, 2));
            mt = fmaxf(mt, __shfl_xor_sync(0xffffffffu, mt, 4));
            mt = fmaxf(mt, __shfl_xor_sync(0xffffffffu, mt, 8));
            float mnew = fmaxf(m[i], mt);
            float corr = __expf(m[i] - mnew);
            float ls = 0.0f;
            #pragma unroll
            for (int j = 0; j < 4; j++) { s[i][j] = __expf(s[i][j] - mnew); ls += s[i][j]; }
            ls += __shfl_xor_sync(0xffffffffu, ls, 1);
            ls += __shfl_xor_sync(0xffffffffu, ls, 2);
            ls += __shfl_xor_sync(0xffffffffu, ls, 4);
            ls += __shfl_xor_sync(0xffffffffu, ls, 8);
            l[i] = l[i] * corr + ls;
            m[i] = mnew;
            #pragma unroll
            for (int j = 0; j < 4; j++) acc[i][j] *= corr;
        }

        __syncthreads();   // all threads done reading sK
        #pragma unroll
        for (int i = 0; i < 4; i++) {
            float4 pv = make_float4(s[i][0], s[i][1], s[i][2], s[i][3]);
            *(float4*)&sK[SWIDX(ty*4+i, tx)] = pv;   // P into K buffer
        }
        __syncthreads();

        // --- PV: acc[i][j] += sum_k P[ty*4+i][k] * V[k][tx*4+j]
        #pragma unroll
        for (int k4 = 0; k4 < 16; k4++) {
            float4 pa[4], va[4];
            #pragma unroll
            for (int i = 0; i < 4; i++)
                pa[i] = *(const float4*)&sK[SWIDX(ty*4+i, k4)];
            #pragma unroll
            for (int u = 0; u < 4; u++)
                va[u] = *(const float4*)&sV[SWIDX(k4*4+u, tx)];
            #pragma unroll
            for (int i = 0; i < 4; i++) {
                float p0 = pa[i].x, p1 = pa[i].y, p2 = pa[i].z, p3 = pa[i].w;
                acc[i][0] += p0*va[0].x + p1*va[1].x + p2*va[2].x + p3*va[3].x;
                acc[i][1] += p0*va[0].y + p1*va[1].y + p2*va[2].y + p3*va[3].y;
                acc[i][2] += p0*va[0].z + p1*va[1].z + p2*va[2].z + p3*va[3].z;
                acc[i][3] += p0*va[0].w + p1*va[1].w + p2*va[2].w + p3*va[3].w;
            }
        }
    }

    // Normalize and write [B,T,D]
    const int b = bh / NH, h = bh % NH;
    #pragma unroll
    for (int i = 0; i < 4; i++) {
        int trow = qt*64 + ty*4 + i;
        float inv = 1.0f / l[i];
        float4 o;
        o.x = acc[i][0]*inv; o.y = acc[i][1]*inv;
        o.z = acc[i][2]*inv; o.w = acc[i][3]*inv;
        *(float4*)&g_att[((size_t)b*TSEQ + trow)*DMOD + h*HDIM + tx*4] = o;
    }
}

// ---------------------------------------------------------------------------
extern "C" void kernel_launch(void* const* d_in, const int* in_sizes, int n_in,
                              void* d_out, int out_size) {
    (void)in_sizes; (void)n_in; (void)out_size;
    const float* x     = (const float*)d_in[0];
    const float* Wkqv  = (const float*)d_in[1];
    const float* bkqv  = (const float*)d_in[2];
    const float* Wproj = (const float*)d_in[3];
    const float* bproj = (const float*)d_in[4];
    float* out = (float*)d_out;

    gemm_qkv_k <<<dim3(3*DMOD/128, MTOK/128), 256>>>(x, Wkqv, bkqv);
    attn_k     <<<dim3(TSEQ/64, BSZ*NH),      256>>>();
    gemm_proj_k<<<dim3(DMOD/128,  MTOK/128),  256>>>(Wproj, bproj, out);
}

// round 5
// speedup vs baseline: 3.0011x; 1.4829x over previous
#include <cuda_runtime.h>
#include <cstdint>
#include <math.h>

#define BSZ   2
#define TSEQ  2048
#define DMOD  1024
#define NH    16
#define HDIM  64
#define MTOK  (BSZ*TSEQ)      /* 4096 */

// Scratch (device globals — no allocations allowed)
__device__ float g_q[(size_t)BSZ*NH*TSEQ*HDIM];   // [B,H,T,64] (Q pre-scaled by 1/8)
__device__ float g_k[(size_t)BSZ*NH*TSEQ*HDIM];
__device__ float g_v[(size_t)BSZ*NH*TSEQ*HDIM];
__device__ float g_att[(size_t)MTOK*DMOD];        // [B,T,D] (tf32-rounded)
__device__ float g_xr[(size_t)MTOK*DMOD];         // x, tf32-rounded
__device__ float g_wkqvT[(size_t)3*DMOD*DMOD];    // W_kqv^T  [3072,1024] (tf32-rounded)
__device__ float g_wprojT[(size_t)DMOD*DMOD];     // W_proj^T [1024,1024] (tf32-rounded)

// ===========================================================================
// Helpers
// ===========================================================================
__device__ __forceinline__ uint32_t smem_u32(const void* p) {
    uint32_t a;
    asm("{ .reg .u64 t; cvta.to.shared.u64 t, %1; cvt.u32.u64 %0, t; }"
        : "=r"(a) : "l"(p));
    return a;
}
__device__ __forceinline__ float tf32r(float x) {
    uint32_t u;
    asm("cvt.rna.tf32.f32 %0, %1;" : "=r"(u) : "f"(x));
    return __uint_as_float(u);
}
__device__ __forceinline__ void cp_async16(uint32_t sdst, const void* gsrc) {
    asm volatile("cp.async.cg.shared.global [%0], [%1], 16;" :: "r"(sdst), "l"(gsrc));
}
__device__ __forceinline__ void ldsm_x4(uint32_t* r, uint32_t addr) {
    asm volatile("ldmatrix.sync.aligned.m8n8.x4.b16 {%0,%1,%2,%3}, [%4];"
                 : "=r"(r[0]), "=r"(r[1]), "=r"(r[2]), "=r"(r[3]) : "r"(addr));
}
__device__ __forceinline__ void mma_tf32(float* c, const uint32_t* a, const uint32_t* b) {
    asm volatile("mma.sync.aligned.m16n8k8.row.col.f32.tf32.tf32.f32 "
                 "{%0,%1,%2,%3}, {%4,%5,%6,%7}, {%8,%9}, {%0,%1,%2,%3};"
                 : "+f"(c[0]), "+f"(c[1]), "+f"(c[2]), "+f"(c[3])
                 : "r"(a[0]), "r"(a[1]), "r"(a[2]), "r"(a[3]), "r"(b[0]), "r"(b[1]));
}

// ===========================================================================
// Pre-passes: tf32-round x; transpose + round weights.
// ===========================================================================
__global__ __launch_bounds__(256) void round_x_k(const float* __restrict__ x) {
    int i = (blockIdx.x * 256 + threadIdx.x) * 4;
    float4 v = *(const float4*)&x[i];
    v.x = tf32r(v.x); v.y = tf32r(v.y); v.z = tf32r(v.z); v.w = tf32r(v.w);
    *(float4*)&g_xr[i] = v;
}

// D[C,R] = round(S[R,C]^T). sel: 0 -> g_wkqvT, 1 -> g_wprojT
__global__ __launch_bounds__(256) void transpose_k(const float* __restrict__ S,
                                                   int R, int C, int sel) {
    __shared__ float t[32][33];
    float* D = sel ? g_wprojT : g_wkqvT;
    const int txx = threadIdx.x & 31;
    const int tyy = threadIdx.x >> 5;
    const int x  = blockIdx.x * 32 + txx;
    const int y0 = blockIdx.y * 32;
    #pragma unroll
    for (int i = tyy; i < 32; i += 8)
        t[i][txx] = S[(size_t)(y0 + i) * C + x];
    __syncthreads();
    const int xo  = y0 + txx;
    const int yo0 = blockIdx.x * 32;
    #pragma unroll
    for (int i = tyy; i < 32; i += 8)
        D[(size_t)(yo0 + i) * R + xo] = tf32r(t[txx][i]);
}

// ===========================================================================
// tf32 mma.sync GEMM body: C(128x128) = A[m0:+128, :K] @ BT[n0:+128, :K]^T
// 8 warps: wm = (wid&1)*64, wn = (wid>>1)*32. Warp tile 64x32 =
// 4 m-atoms x 4 n-atoms of m16n8k8. KC=16, double-buffered cp.async.
// Smem row stride 20 floats -> conflict-free ldmatrix.
// ===========================================================================
#define KC 16
#define SSTR 20

__device__ __forceinline__ void gemm_load_stage(const float* __restrict__ A,
                                                const float* __restrict__ BT,
                                                float* As, float* Bs,
                                                int m0, int n0, int K, int k0) {
    const int tid = threadIdx.x;
    #pragma unroll
    for (int r = 0; r < 2; r++) {
        int idx = tid + r * 256;          // 0..511
        int row = idx >> 2, c4 = idx & 3;
        cp_async16(smem_u32(&As[row * SSTR + c4 * 4]),
                   &A[(size_t)(m0 + row) * K + k0 + c4 * 4]);
        cp_async16(smem_u32(&Bs[row * SSTR + c4 * 4]),
                   &BT[(size_t)(n0 + row) * K + k0 + c4 * 4]);
    }
    asm volatile("cp.async.commit_group;" ::: "memory");
}

__device__ __forceinline__ void gemm_compute_stage(const float* As, const float* Bs,
                                                   int wm, int wn, int lane,
                                                   float c[4][4][4]) {
    #pragma unroll
    for (int oct = 0; oct < 2; oct++) {
        const int k0 = oct * 8;
        uint32_t a[4][4];
        #pragma unroll
        for (int am = 0; am < 4; am++) {
            // matrices: (rows+0,klo),(rows+8,klo),(rows+0,khi),(rows+8,khi)
            int row = wm + am * 16 + ((lane >> 3) & 1) * 8 + (lane & 7);
            int col = k0 + (lane >> 4) * 4;
            ldsm_x4(a[am], smem_u32(&As[row * SSTR + col]));
        }
        uint32_t b[4][2];
        #pragma unroll
        for (int p = 0; p < 2; p++) {
            // matrices: (n+0,klo),(n+0,khi),(n+8,klo),(n+8,khi)
            int row = wn + p * 16 + ((lane >> 4) & 1) * 8 + (lane & 7);
            int col = k0 + ((lane >> 3) & 1) * 4;
            uint32_t r[4];
            ldsm_x4(r, smem_u32(&Bs[row * SSTR + col]));
            b[2*p    ][0] = r[0]; b[2*p    ][1] = r[1];
            b[2*p + 1][0] = r[2]; b[2*p + 1][1] = r[3];
        }
        #pragma unroll
        for (int am = 0; am < 4; am++)
            #pragma unroll
            for (int an = 0; an < 4; an++)
                mma_tf32(c[am][an], a[am], b[an]);
    }
}

__device__ __forceinline__ void gemm_mma_body(const float* __restrict__ A,
                                              const float* __restrict__ BT,
                                              int m0, int n0, int K,
                                              float c[4][4][4]) {
    __shared__ __align__(16) float As[2][128 * SSTR];
    __shared__ __align__(16) float Bs[2][128 * SSTR];
    const int lane = threadIdx.x & 31;
    const int wid  = threadIdx.x >> 5;
    const int wm = (wid & 1) * 64;
    const int wn = (wid >> 1) * 32;

    gemm_load_stage(A, BT, As[0], Bs[0], m0, n0, K, 0);
    const int nk = K / KC;
    for (int kt = 0; kt < nk; kt++) {
        if (kt + 1 < nk) {
            gemm_load_stage(A, BT, As[(kt+1)&1], Bs[(kt+1)&1], m0, n0, K, (kt+1)*KC);
            asm volatile("cp.async.wait_group 1;" ::: "memory");
        } else {
            asm volatile("cp.async.wait_group 0;" ::: "memory");
        }
        __syncthreads();
        gemm_compute_stage(As[kt&1], Bs[kt&1], wm, wn, lane, c);
        __syncthreads();
    }
}

// QKV GEMM: qkv = xr @ WkqvT^T + b, scattered to g_q/g_k/g_v as [B,H,T,64].
__global__ __launch_bounds__(256) void gemm_qkv_mma(const float* __restrict__ bias) {
    float c[4][4][4] = {};
    const int m0 = blockIdx.y * 128, n0 = blockIdx.x * 128;
    gemm_mma_body(g_xr, g_wkqvT, m0, n0, DMOD, c);
    const int lane = threadIdx.x & 31;
    const int wid  = threadIdx.x >> 5;
    const int wm = (wid & 1) * 64, wn = (wid >> 1) * 32;
    #pragma unroll
    for (int an = 0; an < 4; an++) {
        int cb = n0 + wn + an * 8 + (lane & 3) * 2;
        int which = cb >> 10;
        int h  = (cb >> 6) & (NH - 1);
        int ch = cb & 63;
        float* dst = (which == 0) ? g_q : ((which == 1) ? g_k : g_v);
        float qs = (which == 0) ? 0.125f : 1.0f;
        float2 bb = *(const float2*)&bias[cb];
        #pragma unroll
        for (int am = 0; am < 4; am++) {
            #pragma unroll
            for (int hf = 0; hf < 2; hf++) {
                int m = m0 + wm + am * 16 + (lane >> 2) + hf * 8;
                int b = m >> 11, t = m & (TSEQ - 1);
                float2 v;
                v.x = (c[am][an][2*hf + 0] + bb.x) * qs;
                v.y = (c[am][an][2*hf + 1] + bb.y) * qs;
                *(float2*)&dst[((size_t)(b * NH + h) * TSEQ + t) * HDIM + ch] = v;
            }
        }
    }
}

// Output projection: out = g_att @ WprojT^T + b
__global__ __launch_bounds__(256) void gemm_proj_mma(const float* __restrict__ bias,
                                                     float* __restrict__ C) {
    float c[4][4][4] = {};
    const int m0 = blockIdx.y * 128, n0 = blockIdx.x * 128;
    gemm_mma_body(g_att, g_wprojT, m0, n0, DMOD, c);
    const int lane = threadIdx.x & 31;
    const int wid  = threadIdx.x >> 5;
    const int wm = (wid & 1) * 64, wn = (wid >> 1) * 32;
    #pragma unroll
    for (int an = 0; an < 4; an++) {
        int cb = n0 + wn + an * 8 + (lane & 3) * 2;
        float2 bb = *(const float2*)&bias[cb];
        #pragma unroll
        for (int am = 0; am < 4; am++) {
            #pragma unroll
            for (int hf = 0; hf < 2; hf++) {
                int m = m0 + wm + am * 16 + (lane >> 2) + hf * 8;
                float2 v;
                v.x = c[am][an][2*hf + 0] + bb.x;
                v.y = c[am][an][2*hf + 1] + bb.y;
                *(float2*)&C[(size_t)m * DMOD + cb] = v;
            }
        }
    }
}

// ===========================================================================
// GEMM-ified flash attention (identical to the passing R2 version, plus
// tf32 rounding of the output so the proj GEMM sees pre-rounded inputs).
// ===========================================================================
#define SWIDX(r,q) (((r) << 6) + ((((q) ^ (((r) >> 2) & 7))) << 2))

__global__ __launch_bounds__(256) void attn_k() {
    __shared__ float sQ[64*64];
    __shared__ float sK[64*64];
    __shared__ float sV[64*64];

    const int qt  = blockIdx.x;
    const int bh  = blockIdx.y;
    const int tid = threadIdx.x;
    const int tx  = tid & 15;
    const int ty  = tid >> 4;

    const float* Qb = g_q + (size_t)bh * TSEQ * HDIM + (size_t)qt * 64 * HDIM;
    const float* Kb = g_k + (size_t)bh * TSEQ * HDIM;
    const float* Vb = g_v + (size_t)bh * TSEQ * HDIM;

    {
        const float4* Qt = (const float4*)Qb;
        #pragma unroll
        for (int r = 0; r < 4; r++) {
            int f = tid + r * 256;
            int row = f >> 4, q = f & 15;
            *(float4*)&sQ[SWIDX(row, q)] = Qt[f];
        }
    }

    float m[4], l[4], acc[4][4];
    #pragma unroll
    for (int i = 0; i < 4; i++) {
        m[i] = -1e30f; l[i] = 0.0f;
        #pragma unroll
        for (int j = 0; j < 4; j++) acc[i][j] = 0.0f;
    }

    for (int kt = 0; kt <= qt; kt++) {
        __syncthreads();
        {
            const float4* Kt = (const float4*)(Kb + (size_t)kt * 64 * HDIM);
            const float4* Vt = (const float4*)(Vb + (size_t)kt * 64 * HDIM);
            #pragma unroll
            for (int r = 0; r < 4; r++) {
                int f = tid + r * 256;
                int row = f >> 4, q = f & 15;
                *(float4*)&sK[SWIDX(row, q)] = Kt[f];
                *(float4*)&sV[SWIDX(row, q)] = Vt[f];
            }
        }
        __syncthreads();

        float s[4][4] = {};
        #pragma unroll
        for (int q4 = 0; q4 < 16; q4++) {
            float4 qa[4], ka[4];
            #pragma unroll
            for (int i = 0; i < 4; i++)
                qa[i] = *(const float4*)&sQ[SWIDX(ty*4+i, q4)];
            #pragma unroll
            for (int j = 0; j < 4; j++)
                ka[j] = *(const float4*)&sK[SWIDX(tx*4+j, q4)];
            #pragma unroll
            for (int i = 0; i < 4; i++)
                #pragma unroll
                for (int j = 0; j < 4; j++)
                    s[i][j] += qa[i].x*ka[j].x + qa[i].y*ka[j].y
                             + qa[i].z*ka[j].z + qa[i].w*ka[j].w;
        }

        if (kt == qt) {
            #pragma unroll
            for (int i = 0; i < 4; i++) {
                int rg = ty*4 + i;
                #pragma unroll
                for (int j = 0; j < 4; j++)
                    if (tx*4 + j > rg) s[i][j] = -1e30f;
            }
        }

        #pragma unroll
        for (int i = 0; i < 4; i++) {
            float mt = fmaxf(fmaxf(s[i][0], s[i][1]), fmaxf(s[i][2], s[i][3]));
            mt = fmaxf(mt, __shfl_xor_sync(0xffffffffu, mt, 1));
            mt = fmaxf(mt, __shfl_xor_sync(0xffffffffu, mt, 2));
            mt = fmaxf(mt, __shfl_xor_sync(0xffffffffu, mt, 4));
            mt = fmaxf(mt, __shfl_xor_sync(0xffffffffu, mt, 8));
            float mnew = fmaxf(m[i], mt);
            float corr = __expf(m[i] - mnew);
            float ls = 0.0f;
            #pragma unroll
            for (int j = 0; j < 4; j++) { s[i][j] = __expf(s[i][j] - mnew); ls += s[i][j]; }
            ls += __shfl_xor_sync(0xffffffffu, ls, 1);
            ls += __shfl_xor_sync(0xffffffffu, ls, 2);
            ls += __shfl_xor_sync(0xffffffffu, ls, 4);
            ls += __shfl_xor_sync(0xffffffffu, ls, 8);
            l[i] = l[i] * corr + ls;
            m[i] = mnew;
            #pragma unroll
            for (int j = 0; j < 4; j++) acc[i][j] *= corr;
        }

        __syncthreads();
        #pragma unroll
        for (int i = 0; i < 4; i++) {
            float4 pv = make_float4(s[i][0], s[i][1], s[i][2], s[i][3]);
            *(float4*)&sK[SWIDX(ty*4+i, tx)] = pv;
        }
        __syncthreads();

        #pragma unroll
        for (int k4 = 0; k4 < 16; k4++) {
            float4 pa[4], va[4];
            #pragma unroll
            for (int i = 0; i < 4; i++)
                pa[i] = *(const float4*)&sK[SWIDX(ty*4+i, k4)];
            #pragma unroll
            for (int u = 0; u < 4; u++)
                va[u] = *(const float4*)&sV[SWIDX(k4*4+u, tx)];
            #pragma unroll
            for (int i = 0; i < 4; i++) {
                float p0 = pa[i].x, p1 = pa[i].y, p2 = pa[i].z, p3 = pa[i].w;
                acc[i][0] += p0*va[0].x + p1*va[1].x + p2*va[2].x + p3*va[3].x;
                acc[i][1] += p0*va[0].y + p1*va[1].y + p2*va[2].y + p3*va[3].y;
                acc[i][2] += p0*va[0].z + p1*va[1].z + p2*va[2].z + p3*va[3].z;
                acc[i][3] += p0*va[0].w + p1*va[1].w + p2*va[2].w + p3*va[3].w;
            }
        }
    }

    const int b = bh / NH, h = bh % NH;
    #pragma unroll
    for (int i = 0; i < 4; i++) {
        int trow = qt*64 + ty*4 + i;
        float inv = 1.0f / l[i];
        float4 o;
        o.x = tf32r(acc[i][0]*inv); o.y = tf32r(acc[i][1]*inv);
        o.z = tf32r(acc[i][2]*inv); o.w = tf32r(acc[i][3]*inv);
        *(float4*)&g_att[((size_t)b*TSEQ + trow)*DMOD + h*HDIM + tx*4] = o;
    }
}

// ---------------------------------------------------------------------------
extern "C" void kernel_launch(void* const* d_in, const int* in_sizes, int n_in,
                              void* d_out, int out_size) {
    (void)in_sizes; (void)n_in; (void)out_size;
    const float* x     = (const float*)d_in[0];
    const float* Wkqv  = (const float*)d_in[1];
    const float* bkqv  = (const float*)d_in[2];
    const float* Wproj = (const float*)d_in[3];
    const float* bproj = (const float*)d_in[4];
    float* out = (float*)d_out;

    round_x_k   <<<MTOK*DMOD/1024, 256>>>(x);
    transpose_k <<<dim3(3*DMOD/32, DMOD/32), 256>>>(Wkqv,  DMOD, 3*DMOD, 0);
    transpose_k <<<dim3(DMOD/32,   DMOD/32), 256>>>(Wproj, DMOD, DMOD,   1);

    gemm_qkv_mma <<<dim3(3*DMOD/128, MTOK/128), 256>>>(bkqv);
    attn_k       <<<dim3(TSEQ/64, BSZ*NH),      256>>>();
    gemm_proj_mma<<<dim3(DMOD/128,  MTOK/128),  256>>>(bproj, out);
}

// round 6
// speedup vs baseline: 5.5765x; 1.8582x over previous
#include <cuda_runtime.h>
#include <cstdint>
#include <math.h>

#define BSZ   2
#define TSEQ  2048
#define DMOD  1024
#define NH    16
#define HDIM  64
#define MTOK  (BSZ*TSEQ)      /* 4096 */

// Scratch (device globals — no allocations allowed)
__device__ float g_q[(size_t)BSZ*NH*TSEQ*HDIM];   // [B,H,T,64] (Q pre-scaled by 1/8, tf32)
__device__ float g_k[(size_t)BSZ*NH*TSEQ*HDIM];   // [B,H,T,64] (tf32)
__device__ float g_vT[(size_t)BSZ*NH*HDIM*TSEQ];  // [B,H,64,T] (tf32, t-major!)
__device__ float g_att[(size_t)MTOK*DMOD];        // [B,T,D] (tf32-rounded)
__device__ float g_xr[(size_t)MTOK*DMOD];         // x, tf32-rounded
__device__ float g_wkqvT[(size_t)3*DMOD*DMOD];    // W_kqv^T  [3072,1024] (tf32)
__device__ float g_wprojT[(size_t)DMOD*DMOD];     // W_proj^T [1024,1024] (tf32)

// ===========================================================================
// Helpers
// ===========================================================================
__device__ __forceinline__ uint32_t smem_u32(const void* p) {
    uint32_t a;
    asm("{ .reg .u64 t; cvta.to.shared.u64 t, %1; cvt.u32.u64 %0, t; }"
        : "=r"(a) : "l"(p));
    return a;
}
__device__ __forceinline__ float tf32r(float x) {
    uint32_t u;
    asm("cvt.rna.tf32.f32 %0, %1;" : "=r"(u) : "f"(x));
    return __uint_as_float(u);
}
__device__ __forceinline__ void cp_async16(uint32_t sdst, const void* gsrc) {
    asm volatile("cp.async.cg.shared.global [%0], [%1], 16;" :: "r"(sdst), "l"(gsrc));
}
__device__ __forceinline__ void ldsm_x4(uint32_t* r, uint32_t addr) {
    asm volatile("ldmatrix.sync.aligned.m8n8.x4.b16 {%0,%1,%2,%3}, [%4];"
                 : "=r"(r[0]), "=r"(r[1]), "=r"(r[2]), "=r"(r[3]) : "r"(addr));
}
__device__ __forceinline__ void mma_tf32(float* c, const uint32_t* a, const uint32_t* b) {
    asm volatile("mma.sync.aligned.m16n8k8.row.col.f32.tf32.tf32.f32 "
                 "{%0,%1,%2,%3}, {%4,%5,%6,%7}, {%8,%9}, {%0,%1,%2,%3};"
                 : "+f"(c[0]), "+f"(c[1]), "+f"(c[2]), "+f"(c[3])
                 : "r"(a[0]), "r"(a[1]), "r"(a[2]), "r"(a[3]), "r"(b[0]), "r"(b[1]));
}

// ===========================================================================
// Pre-passes: tf32-round x; transpose + round weights.
// ===========================================================================
__global__ __launch_bounds__(256) void round_x_k(const float* __restrict__ x) {
    int i = (blockIdx.x * 256 + threadIdx.x) * 4;
    float4 v = *(const float4*)&x[i];
    v.x = tf32r(v.x); v.y = tf32r(v.y); v.z = tf32r(v.z); v.w = tf32r(v.w);
    *(float4*)&g_xr[i] = v;
}

// D[C,R] = round(S[R,C]^T). sel: 0 -> g_wkqvT, 1 -> g_wprojT
__global__ __launch_bounds__(256) void transpose_k(const float* __restrict__ S,
                                                   int R, int C, int sel) {
    __shared__ float t[32][33];
    float* D = sel ? g_wprojT : g_wkqvT;
    const int txx = threadIdx.x & 31;
    const int tyy = threadIdx.x >> 5;
    const int x  = blockIdx.x * 32 + txx;
    const int y0 = blockIdx.y * 32;
    #pragma unroll
    for (int i = tyy; i < 32; i += 8)
        t[i][txx] = S[(size_t)(y0 + i) * C + x];
    __syncthreads();
    const int xo  = y0 + txx;
    const int yo0 = blockIdx.x * 32;
    #pragma unroll
    for (int i = tyy; i < 32; i += 8)
        D[(size_t)(yo0 + i) * R + xo] = tf32r(t[txx][i]);
}

// ===========================================================================
// tf32 mma.sync GEMM body (unchanged from passing R5 version).
// ===========================================================================
#define KC 16
#define SSTR 20

__device__ __forceinline__ void gemm_load_stage(const float* __restrict__ A,
                                                const float* __restrict__ BT,
                                                float* As, float* Bs,
                                                int m0, int n0, int K, int k0) {
    const int tid = threadIdx.x;
    #pragma unroll
    for (int r = 0; r < 2; r++) {
        int idx = tid + r * 256;
        int row = idx >> 2, c4 = idx & 3;
        cp_async16(smem_u32(&As[row * SSTR + c4 * 4]),
                   &A[(size_t)(m0 + row) * K + k0 + c4 * 4]);
        cp_async16(smem_u32(&Bs[row * SSTR + c4 * 4]),
                   &BT[(size_t)(n0 + row) * K + k0 + c4 * 4]);
    }
    asm volatile("cp.async.commit_group;" ::: "memory");
}

__device__ __forceinline__ void gemm_compute_stage(const float* As, const float* Bs,
                                                   int wm, int wn, int lane,
                                                   float c[4][4][4]) {
    #pragma unroll
    for (int oct = 0; oct < 2; oct++) {
        const int k0 = oct * 8;
        uint32_t a[4][4];
        #pragma unroll
        for (int am = 0; am < 4; am++) {
            int row = wm + am * 16 + ((lane >> 3) & 1) * 8 + (lane & 7);
            int col = k0 + (lane >> 4) * 4;
            ldsm_x4(a[am], smem_u32(&As[row * SSTR + col]));
        }
        uint32_t b[4][2];
        #pragma unroll
        for (int p = 0; p < 2; p++) {
            int row = wn + p * 16 + ((lane >> 4) & 1) * 8 + (lane & 7);
            int col = k0 + ((lane >> 3) & 1) * 4;
            uint32_t r[4];
            ldsm_x4(r, smem_u32(&Bs[row * SSTR + col]));
            b[2*p    ][0] = r[0]; b[2*p    ][1] = r[1];
            b[2*p + 1][0] = r[2]; b[2*p + 1][1] = r[3];
        }
        #pragma unroll
        for (int am = 0; am < 4; am++)
            #pragma unroll
            for (int an = 0; an < 4; an++)
                mma_tf32(c[am][an], a[am], b[an]);
    }
}

__device__ __forceinline__ void gemm_mma_body(const float* __restrict__ A,
                                              const float* __restrict__ BT,
                                              int m0, int n0, int K,
                                              float c[4][4][4]) {
    __shared__ __align__(16) float As[2][128 * SSTR];
    __shared__ __align__(16) float Bs[2][128 * SSTR];
    const int lane = threadIdx.x & 31;
    const int wid  = threadIdx.x >> 5;
    const int wm = (wid & 1) * 64;
    const int wn = (wid >> 1) * 32;

    gemm_load_stage(A, BT, As[0], Bs[0], m0, n0, K, 0);
    const int nk = K / KC;
    for (int kt = 0; kt < nk; kt++) {
        if (kt + 1 < nk) {
            gemm_load_stage(A, BT, As[(kt+1)&1], Bs[(kt+1)&1], m0, n0, K, (kt+1)*KC);
            asm volatile("cp.async.wait_group 1;" ::: "memory");
        } else {
            asm volatile("cp.async.wait_group 0;" ::: "memory");
        }
        __syncthreads();
        gemm_compute_stage(As[kt&1], Bs[kt&1], wm, wn, lane, c);
        __syncthreads();
    }
}

// QKV GEMM epilogue: q/k -> [B,H,T,64] tf32-rounded (q pre-scaled 1/8);
// v -> g_vT [B,H,64,T] tf32-rounded.
__global__ __launch_bounds__(256) void gemm_qkv_mma(const float* __restrict__ bias) {
    float c[4][4][4] = {};
    const int m0 = blockIdx.y * 128, n0 = blockIdx.x * 128;
    gemm_mma_body(g_xr, g_wkqvT, m0, n0, DMOD, c);
    const int lane = threadIdx.x & 31;
    const int wid  = threadIdx.x >> 5;
    const int wm = (wid & 1) * 64, wn = (wid >> 1) * 32;
    #pragma unroll
    for (int an = 0; an < 4; an++) {
        int cb = n0 + wn + an * 8 + (lane & 3) * 2;
        int which = cb >> 10;
        int h  = (cb >> 6) & (NH - 1);
        int ch = cb & 63;
        float2 bb = *(const float2*)&bias[cb];
        #pragma unroll
        for (int am = 0; am < 4; am++) {
            #pragma unroll
            for (int hf = 0; hf < 2; hf++) {
                int m = m0 + wm + am * 16 + (lane >> 2) + hf * 8;
                int b = m >> 11, t = m & (TSEQ - 1);
                float vx = c[am][an][2*hf + 0] + bb.x;
                float vy = c[am][an][2*hf + 1] + bb.y;
                if (which == 2) {
                    size_t vb = (size_t)(b * NH + h) * HDIM;
                    g_vT[(vb + ch    ) * TSEQ + t] = tf32r(vx);
                    g_vT[(vb + ch + 1) * TSEQ + t] = tf32r(vy);
                } else {
                    float* dst = (which == 0) ? g_q : g_k;
                    float qs = (which == 0) ? 0.125f : 1.0f;
                    float2 v;
                    v.x = tf32r(vx * qs);
                    v.y = tf32r(vy * qs);
                    *(float2*)&dst[((size_t)(b * NH + h) * TSEQ + t) * HDIM + ch] = v;
                }
            }
        }
    }
}

// Output projection: out = g_att @ WprojT^T + b
__global__ __launch_bounds__(256) void gemm_proj_mma(const float* __restrict__ bias,
                                                     float* __restrict__ C) {
    float c[4][4][4] = {};
    const int m0 = blockIdx.y * 128, n0 = blockIdx.x * 128;
    gemm_mma_body(g_att, g_wprojT, m0, n0, DMOD, c);
    const int lane = threadIdx.x & 31;
    const int wid  = threadIdx.x >> 5;
    const int wm = (wid & 1) * 64, wn = (wid >> 1) * 32;
    #pragma unroll
    for (int an = 0; an < 4; an++) {
        int cb = n0 + wn + an * 8 + (lane & 3) * 2;
        float2 bb = *(const float2*)&bias[cb];
        #pragma unroll
        for (int am = 0; am < 4; am++) {
            #pragma unroll
            for (int hf = 0; hf < 2; hf++) {
                int m = m0 + wm + am * 16 + (lane >> 2) + hf * 8;
                float2 v;
                v.x = c[am][an][2*hf + 0] + bb.x;
                v.y = c[am][an][2*hf + 1] + bb.y;
                *(float2*)&C[(size_t)m * DMOD + cb] = v;
            }
        }
    }
}

// ===========================================================================
// mma.sync flash attention. CTA = 64 q-rows x one (b,h); 4 warps x 16 q-rows.
// k-tiles of 64. Q in registers as A-fragments. S mma -> softmax on register
// layout -> P (tf32-rounded) into K buffer -> PV mma with V^T tiles from
// g_vT (pre-transposed in QKV epilogue). Smem stride 68 -> conflict-free
// ldmatrix phases.
// ===========================================================================
#define ATSTR 68

__global__ __launch_bounds__(128) void attn_mma() {
    __shared__ __align__(16) float Ks[64 * ATSTR];   // K tile, reused for P
    __shared__ __align__(16) float Vts[64 * ATSTR];  // V^T tile [d][k]

    const int qt  = gridDim.x - 1 - blockIdx.x;      // long rows first
    const int bh  = blockIdx.y;
    const int tid = threadIdx.x;
    const int lane = tid & 31;
    const int w    = tid >> 5;

    const float* Qb  = g_q  + ((size_t)bh * TSEQ + (size_t)qt * 64) * HDIM;
    const float* Kb  = g_k  + (size_t)bh * TSEQ * HDIM;
    const float* VTb = g_vT + (size_t)bh * HDIM * TSEQ;

    // Stage Q through Ks, load A-fragments to registers
    {
        const float4* Qt = (const float4*)Qb;
        #pragma unroll
        for (int r = 0; r < 8; r++) {
            int f = tid + r * 128;
            int row = f >> 4, c4 = f & 15;
            *(float4*)&Ks[row * ATSTR + c4 * 4] = Qt[f];
        }
    }
    __syncthreads();
    uint32_t qf[8][4];
    {
        int row = w * 16 + ((lane >> 3) & 1) * 8 + (lane & 7);
        #pragma unroll
        for (int oct = 0; oct < 8; oct++)
            ldsm_x4(qf[oct], smem_u32(&Ks[row * ATSTR + oct * 8 + (lane >> 4) * 4]));
    }

    float mst[2] = {-1e30f, -1e30f}, lst[2] = {0.f, 0.f};
    float o[8][4];
    #pragma unroll
    for (int an = 0; an < 8; an++)
        #pragma unroll
        for (int e = 0; e < 4; e++) o[an][e] = 0.f;

    for (int kt = 0; kt <= qt; kt++) {
        __syncthreads();   // prev iter done reading Ks(P)/Vts; Q frags loaded
        {
            const float4* Kt = (const float4*)(Kb + (size_t)kt * 64 * HDIM);
            #pragma unroll
            for (int r = 0; r < 8; r++) {
                int f = tid + r * 128;
                int row = f >> 4, c4 = f & 15;
                *(float4*)&Ks[row * ATSTR + c4 * 4] = Kt[f];
                const float4* Vr = (const float4*)(VTb + (size_t)row * TSEQ + kt * 64);
                *(float4*)&Vts[row * ATSTR + c4 * 4] = Vr[c4];
            }
        }
        __syncthreads();

        // --- S = Q K^T (warp: 16q x 64k)
        float c[8][4];
        #pragma unroll
        for (int an = 0; an < 8; an++)
            #pragma unroll
            for (int e = 0; e < 4; e++) c[an][e] = 0.f;
        #pragma unroll
        for (int oct = 0; oct < 8; oct++) {
            uint32_t b[8][2];
            #pragma unroll
            for (int p = 0; p < 4; p++) {
                int row = p * 16 + ((lane >> 4) & 1) * 8 + (lane & 7);
                int col = oct * 8 + ((lane >> 3) & 1) * 4;
                uint32_t t4[4];
                ldsm_x4(t4, smem_u32(&Ks[row * ATSTR + col]));
                b[2*p    ][0] = t4[0]; b[2*p    ][1] = t4[1];
                b[2*p + 1][0] = t4[2]; b[2*p + 1][1] = t4[3];
            }
            #pragma unroll
            for (int an = 0; an < 8; an++) mma_tf32(c[an], qf[oct], b[an]);
        }

        // --- causal mask (diagonal tile only; same 64-token window)
        if (kt == qt) {
            int r0 = w * 16 + (lane >> 2);
            #pragma unroll
            for (int an = 0; an < 8; an++) {
                int k0 = an * 8 + (lane & 3) * 2;
                if (k0     > r0)     c[an][0] = -1e30f;
                if (k0 + 1 > r0)     c[an][1] = -1e30f;
                if (k0     > r0 + 8) c[an][2] = -1e30f;
                if (k0 + 1 > r0 + 8) c[an][3] = -1e30f;
            }
        }

        // --- online softmax (rows spread over lanes sharing lane>>2)
        #pragma unroll
        for (int h = 0; h < 2; h++) {
            float mt = -1e30f;
            #pragma unroll
            for (int an = 0; an < 8; an++)
                mt = fmaxf(mt, fmaxf(c[an][2*h], c[an][2*h + 1]));
            mt = fmaxf(mt, __shfl_xor_sync(0xffffffffu, mt, 1));
            mt = fmaxf(mt, __shfl_xor_sync(0xffffffffu, mt, 2));
            float mnew = fmaxf(mst[h], mt);
            float corr = __expf(mst[h] - mnew);
            float sum = 0.f;
            #pragma unroll
            for (int an = 0; an < 8; an++) {
                c[an][2*h]     = __expf(c[an][2*h]     - mnew);
                c[an][2*h + 1] = __expf(c[an][2*h + 1] - mnew);
                sum += c[an][2*h] + c[an][2*h + 1];
            }
            sum += __shfl_xor_sync(0xffffffffu, sum, 1);
            sum += __shfl_xor_sync(0xffffffffu, sum, 2);
            lst[h] = lst[h] * corr + sum;
            mst[h] = mnew;
            #pragma unroll
            for (int an = 0; an < 8; an++) {
                o[an][2*h]     *= corr;
                o[an][2*h + 1] *= corr;
            }
        }

        __syncthreads();   // all warps done reading Ks (S mma)
        // --- store P (tf32-rounded) into Ks; warp writes only its own rows
        {
            int r0 = w * 16 + (lane >> 2);
            #pragma unroll
            for (int an = 0; an < 8; an++) {
                int col = an * 8 + (lane & 3) * 2;
                float2 p0, p1;
                p0.x = tf32r(c[an][0]); p0.y = tf32r(c[an][1]);
                p1.x = tf32r(c[an][2]); p1.y = tf32r(c[an][3]);
                *(float2*)&Ks[r0 * ATSTR + col]       = p0;
                *(float2*)&Ks[(r0 + 8) * ATSTR + col] = p1;
            }
        }
        __syncwarp();      // warp-local store->ldmatrix visibility

        // --- O += P V  (A = P rows of this warp, B = Vts [d][k])
        #pragma unroll
        for (int oct = 0; oct < 8; oct++) {
            uint32_t pf[4];
            int arow = w * 16 + ((lane >> 3) & 1) * 8 + (lane & 7);
            ldsm_x4(pf, smem_u32(&Ks[arow * ATSTR + oct * 8 + (lane >> 4) * 4]));
            uint32_t b[8][2];
            #pragma unroll
            for (int p = 0; p < 4; p++) {
                int row = p * 16 + ((lane >> 4) & 1) * 8 + (lane & 7);
                int col = oct * 8 + ((lane >> 3) & 1) * 4;
                uint32_t t4[4];
                ldsm_x4(t4, smem_u32(&Vts[row * ATSTR + col]));
                b[2*p    ][0] = t4[0]; b[2*p    ][1] = t4[1];
                b[2*p + 1][0] = t4[2]; b[2*p + 1][1] = t4[3];
            }
            #pragma unroll
            for (int an = 0; an < 8; an++) mma_tf32(o[an], pf, b[an]);
        }
    }

    // --- epilogue: normalize, tf32-round, write [B,T,D]
    const int b  = bh >> 4;
    const int hd = bh & 15;
    const int r0 = w * 16 + (lane >> 2);
    #pragma unroll
    for (int h = 0; h < 2; h++) {
        float inv = 1.0f / lst[h];
        int t = qt * 64 + r0 + h * 8;
        float* orow = &g_att[((size_t)b * TSEQ + t) * DMOD + hd * HDIM];
        #pragma unroll
        for (int an = 0; an < 8; an++) {
            int d = an * 8 + (lane & 3) * 2;
            float2 v;
            v.x = tf32r(o[an][2*h]     * inv);
            v.y = tf32r(o[an][2*h + 1] * inv);
            *(float2*)&orow[d] = v;
        }
    }
}

// ---------------------------------------------------------------------------
extern "C" void kernel_launch(void* const* d_in, const int* in_sizes, int n_in,
                              void* d_out, int out_size) {
    (void)in_sizes; (void)n_in; (void)out_size;
    const float* x     = (const float*)d_in[0];
    const float* Wkqv  = (const float*)d_in[1];
    const float* bkqv  = (const float*)d_in[2];
    const float* Wproj = (const float*)d_in[3];
    const float* bproj = (const float*)d_in[4];
    float* out = (float*)d_out;

    round_x_k   <<<MTOK*DMOD/1024, 256>>>(x);
    transpose_k <<<dim3(3*DMOD/32, DMOD/32), 256>>>(Wkqv,  DMOD, 3*DMOD, 0);
    transpose_k <<<dim3(DMOD/32,   DMOD/32), 256>>>(Wproj, DMOD, DMOD,   1);

    gemm_qkv_mma <<<dim3(3*DMOD/128, MTOK/128), 256>>>(bkqv);
    attn_mma     <<<dim3(TSEQ/64, BSZ*NH),      128>>>();
    gemm_proj_mma<<<dim3(DMOD/128,  MTOK/128),  256>>>(bproj, out);
}